// round 10
// baseline (speedup 1.0000x reference)
#include <cuda_runtime.h>
#include <math_constants.h>

#define D_FEAT   128
#define K_NEIGH  32
#define WARPS_PER_CTA 4
#define ITEMS_PER_WARP 2

// Map float -> uint preserving order (monotone), so integer max == float max.
__device__ __forceinline__ unsigned order_key(float f) {
    unsigned x = __float_as_uint(f);
    return (x & 0x80000000u) ? ~x : (x | 0x80000000u);
}

// One WARP per TWO batch items (R6 concurrency x R9 structure).
// The kernel is pinned at the practical LTS cap (~12.8 TB/s); this version
// raises per-warp memory-level parallelism: 8 independent float4 row-loads in
// flight per sim pass (4 per item) and a 20-load batched winner gather.
// Sim: 4 rows/item per pass, 8-lane-group butterfly; owner permutation
// lane 8g+p <- row 4p+g (no route shuffle). Exact-sim ties only arise from
// duplicate neighbor indices (identical rows), so owner-order tie-break is
// output-equivalent to jax.lax.top_k row-order.
// Key = dot * rsqrt(||n||^2) (center norm cancels for top-k).
// Selection: fused exact REDUX argmax rounds for both items -> bitmasks;
// then resolve item0's 10 indices, issue its 10 gathers, resolve item1
// (shuffles overlap item0's load latency), issue its 10 gathers.
__global__ __launch_bounds__(WARPS_PER_CTA * 32, 6)
void intra_agg_kernel(const float*  __restrict__ feats,
                      const int*    __restrict__ nodes,
                      const int*    __restrict__ neighs,
                      const int*    __restrict__ nsamp_p,
                      float*        __restrict__ out)
{
    const int lane = threadIdx.x & 31;
    const int warp = threadIdx.x >> 5;
    const int b0   = (blockIdx.x * WARPS_PER_CTA + warp) * ITEMS_PER_WARP;
    const int b1   = b0 + 1;
    const int g    = lane >> 3;        // group 0..3 (which row of the quad)
    const int t    = lane & 7;         // lane within group

    const float4* __restrict__ f4 = reinterpret_cast<const float4*>(feats);

    // ---- center rows: this lane's 16-float column slice of each center ----
    const int node0 = nodes[b0];
    const int node1 = nodes[b1];
    float4 c0[4], c1[4];
    #pragma unroll
    for (int j = 0; j < 4; j++) {
        c0[j] = f4[(size_t)node0 * (D_FEAT / 4) + t + 8 * j];
        c1[j] = f4[(size_t)node1 * (D_FEAT / 4) + t + 8 * j];
    }

    // ---- neighbor indices (lane k holds index k of each item) ----
    const int idx0 = neighs[b0 * K_NEIGH + lane];
    const int idx1 = neighs[b1 * K_NEIGH + lane];

    // ---- similarities: 8 passes; pass p handles row 4p+g of BOTH items ----
    float sim0 = 0.0f, sim1 = 0.0f;
    #pragma unroll
    for (int p = 0; p < K_NEIGH / 4; p++) {
        const int n0 = __shfl_sync(0xffffffffu, idx0, 4 * p + g);
        const int n1 = __shfl_sync(0xffffffffu, idx1, 4 * p + g);
        const float4* __restrict__ r0 = f4 + (size_t)n0 * (D_FEAT / 4);
        const float4* __restrict__ r1 = f4 + (size_t)n1 * (D_FEAT / 4);

        float d0 = 0.f, s0 = 0.f, d1 = 0.f, s1 = 0.f;
        #pragma unroll
        for (int j = 0; j < 4; j++) {
            const float4 v = r0[t + 8 * j];
            d0 = fmaf(v.x, c0[j].x, fmaf(v.y, c0[j].y,
                 fmaf(v.z, c0[j].z, fmaf(v.w, c0[j].w, d0))));
            s0 = fmaf(v.x, v.x, fmaf(v.y, v.y,
                 fmaf(v.z, v.z, fmaf(v.w, v.w, s0))));
            const float4 w = r1[t + 8 * j];
            d1 = fmaf(w.x, c1[j].x, fmaf(w.y, c1[j].y,
                 fmaf(w.z, c1[j].z, fmaf(w.w, c1[j].w, d1))));
            s1 = fmaf(w.x, w.x, fmaf(w.y, w.y,
                 fmaf(w.z, w.z, fmaf(w.w, w.w, s1))));
        }
        // 3-stage butterfly per 8-lane group; 12 shuffles serve 8 rows
        #pragma unroll
        for (int off = 1; off < 8; off <<= 1) {
            d0 += __shfl_xor_sync(0xffffffffu, d0, off);
            s0 += __shfl_xor_sync(0xffffffffu, s0, off);
            d1 += __shfl_xor_sync(0xffffffffu, d1, off);
            s1 += __shfl_xor_sync(0xffffffffu, s1, off);
        }
        if (t == p) {                       // owner lane 8g+p <- row 4p+g
            sim0 = d0 * rsqrtf(s0);
            sim1 = d1 * rsqrtf(s1);
        }
    }

    const int ns = nsamp_p ? *nsamp_p : 10;

    // ---- fused top-ns selection: winner OWNER-lane bitmasks for both items ----
    unsigned u0 = order_key(sim0);
    unsigned u1 = order_key(sim1);
    unsigned wmask0 = 0u, wmask1 = 0u;
    for (int i = 0; i < ns; i++) {
        const unsigned m0  = __reduce_max_sync(0xffffffffu, u0);
        const unsigned m1  = __reduce_max_sync(0xffffffffu, u1);
        const unsigned bm0 = __ballot_sync(0xffffffffu, u0 == m0);
        const unsigned bm1 = __ballot_sync(0xffffffffu, u1 == m1);
        const int w0 = __ffs(bm0) - 1;
        const int w1 = __ffs(bm1) - 1;
        if (lane == w0) u0 = 0u;
        if (lane == w1) u1 = 0u;
        wmask0 |= 1u << w0;
        wmask1 |= 1u << w1;
    }

    // ---- resolve + batched gathers (item0 loads overlap item1 resolution) ----
    float4 a00 = make_float4(0.f, 0.f, 0.f, 0.f);
    float4 a01 = make_float4(0.f, 0.f, 0.f, 0.f);
    float4 a10 = make_float4(0.f, 0.f, 0.f, 0.f);
    float4 a11 = make_float4(0.f, 0.f, 0.f, 0.f);
    if (ns == 10) {                         // fast path: fully unrolled
        int nn[10];
        unsigned wm = wmask0;
        #pragma unroll
        for (int i = 0; i < 10; i++) {
            const int w = __ffs(wm) - 1; wm &= wm - 1;
            nn[i] = __shfl_sync(0xffffffffu, idx0, 4 * (w & 7) + (w >> 3));
        }
        #pragma unroll
        for (int i = 0; i < 10; i++) {
            const float4 v = f4[(size_t)nn[i] * (D_FEAT / 4) + lane];
            if (i & 1) { a01.x += v.x; a01.y += v.y; a01.z += v.z; a01.w += v.w; }
            else       { a00.x += v.x; a00.y += v.y; a00.z += v.z; a00.w += v.w; }
        }
        wm = wmask1;
        #pragma unroll
        for (int i = 0; i < 10; i++) {
            const int w = __ffs(wm) - 1; wm &= wm - 1;
            nn[i] = __shfl_sync(0xffffffffu, idx1, 4 * (w & 7) + (w >> 3));
        }
        #pragma unroll
        for (int i = 0; i < 10; i++) {
            const float4 v = f4[(size_t)nn[i] * (D_FEAT / 4) + lane];
            if (i & 1) { a11.x += v.x; a11.y += v.y; a11.z += v.z; a11.w += v.w; }
            else       { a10.x += v.x; a10.y += v.y; a10.z += v.z; a10.w += v.w; }
        }
    } else {                                // generic path
        int i = 0;
        while (wmask0) {
            const int w = __ffs(wmask0) - 1; wmask0 &= wmask0 - 1;
            const int nn = __shfl_sync(0xffffffffu, idx0, 4 * (w & 7) + (w >> 3));
            const float4 v = f4[(size_t)nn * (D_FEAT / 4) + lane];
            if (i & 1) { a01.x += v.x; a01.y += v.y; a01.z += v.z; a01.w += v.w; }
            else       { a00.x += v.x; a00.y += v.y; a00.z += v.z; a00.w += v.w; }
            i++;
        }
        i = 0;
        while (wmask1) {
            const int w = __ffs(wmask1) - 1; wmask1 &= wmask1 - 1;
            const int nn = __shfl_sync(0xffffffffu, idx1, 4 * (w & 7) + (w >> 3));
            const float4 v = f4[(size_t)nn * (D_FEAT / 4) + lane];
            if (i & 1) { a11.x += v.x; a11.y += v.y; a11.z += v.z; a11.w += v.w; }
            else       { a10.x += v.x; a10.y += v.y; a10.z += v.z; a10.w += v.w; }
            i++;
        }
    }

    // ---- mean + relu, coalesced stores ----
    const float inv = 1.0f / (float)ns;
    float4 r0v, r1v;
    r0v.x = fmaxf((a00.x + a01.x) * inv, 0.0f);
    r0v.y = fmaxf((a00.y + a01.y) * inv, 0.0f);
    r0v.z = fmaxf((a00.z + a01.z) * inv, 0.0f);
    r0v.w = fmaxf((a00.w + a01.w) * inv, 0.0f);
    r1v.x = fmaxf((a10.x + a11.x) * inv, 0.0f);
    r1v.y = fmaxf((a10.y + a11.y) * inv, 0.0f);
    r1v.z = fmaxf((a10.z + a11.z) * inv, 0.0f);
    r1v.w = fmaxf((a10.w + a11.w) * inv, 0.0f);
    reinterpret_cast<float4*>(out)[(size_t)b0 * (D_FEAT / 4) + lane] = r0v;
    reinterpret_cast<float4*>(out)[(size_t)b1 * (D_FEAT / 4) + lane] = r1v;
}

extern "C" void kernel_launch(void* const* d_in, const int* in_sizes, int n_in,
                              void* d_out, int out_size)
{
    const float* feats  = (const float*)d_in[0];   // [N_NODES, 128] f32
    const int*   nodes  = (const int*)d_in[1];     // [B] i32
    const int*   neighs = (const int*)d_in[2];     // [B, 32] i32
    const int*   nsamp  = (n_in > 3) ? (const int*)d_in[3] : nullptr;  // scalar (10)

    const int B = in_sizes[1];                     // 32768
    intra_agg_kernel<<<B / (WARPS_PER_CTA * ITEMS_PER_WARP), WARPS_PER_CTA * 32>>>(
        feats, nodes, neighs, nsamp, (float*)d_out);
}